// round 1
// baseline (speedup 1.0000x reference)
#include <cuda_runtime.h>
#include <cstdint>

// Problem constants (deterministic per setup_inputs)
#define BATCH   4096
#define IDIM    1024
#define LDIM    1024
#define HDIM    2048
#define ODIM    512
#define HALTH   1024
#define OUTER   8
#define INNER   4

// ---------------------------------------------------------------------------
// Scratch (device globals; no allocation allowed)
// ---------------------------------------------------------------------------
__device__ float g_state[BATCH * LDIM];      // 16 MB
__device__ float g_ans[BATCH * ODIM];        // 8 MB
__device__ float g_xg[BATCH * 3 * LDIM];     // 48 MB
__device__ float g_hg[BATCH * 3 * LDIM];     // 48 MB
__device__ float g_h1[BATCH * HDIM];         // 32 MB
__device__ float g_h2[BATCH * HALTH];        // 16 MB

__device__ __forceinline__ uint32_t f2tf32(float x) {
    uint32_t r;
    asm("cvt.rna.tf32.f32 %0, %1;" : "=r"(r) : "f"(x));
    return r;
}

#define EPI_NONE   0
#define EPI_RELU   1
#define EPI_LOGITS 2

// ---------------------------------------------------------------------------
// tf32 mma.sync GEMM:  C[M,N] = epi( A @ W^T + bias )
//   A: [M,K] row-major, logically concat(A1[:, :K1], A2[:, K1:]) along K
//   W: [N,K] row-major
//   BM=BN=128, BK=16, 256 threads (8 warps, 4x2), warp tile 32x64
//   M=4096 fixed multiple of 128; N multiple of 128; K multiple of 16; K1 mult of 16
// ---------------------------------------------------------------------------
template <int EPI>
__global__ void __launch_bounds__(256, 2)
gemm_tf32(const float* __restrict__ A1, int lda1, int K1,
          const float* __restrict__ A2, int lda2,
          const float* __restrict__ W,
          const float* __restrict__ bias,
          float* __restrict__ C,
          float* __restrict__ C2,   // secondary output (tanh(logits) -> ans) for EPI_LOGITS
          int N, int K)
{
    __shared__ uint32_t sA[128 * 20];
    __shared__ uint32_t sB[128 * 20];

    const int tid  = threadIdx.x;
    const int lane = tid & 31;
    const int warp = tid >> 5;
    const int wm   = warp >> 1;  // 0..3
    const int wn   = warp & 1;   // 0..1
    const int row0 = blockIdx.y * 128;
    const int col0 = blockIdx.x * 128;

    float c[2][8][4];
#pragma unroll
    for (int i = 0; i < 2; i++)
#pragma unroll
        for (int j = 0; j < 8; j++)
#pragma unroll
            for (int k = 0; k < 4; k++) c[i][j][k] = 0.0f;

    const int lrow = tid >> 2;        // 0..63 (and +64 for second half)
    const int lcol = (tid & 3) * 4;   // 0,4,8,12

    for (int k0 = 0; k0 < K; k0 += 16) {
        const float* Abase;
        int lda;
        if (k0 < K1) { Abase = A1 + k0;        lda = lda1; }
        else         { Abase = A2 + (k0 - K1); lda = lda2; }

        __syncthreads();  // protect smem reads of previous iteration
#pragma unroll
        for (int h = 0; h < 2; h++) {
            const int r = lrow + h * 64;
            float4 va = *(const float4*)(Abase + (size_t)(row0 + r) * lda + lcol);
            uint4 ta;
            ta.x = f2tf32(va.x); ta.y = f2tf32(va.y);
            ta.z = f2tf32(va.z); ta.w = f2tf32(va.w);
            *(uint4*)&sA[r * 20 + lcol] = ta;

            float4 vw = *(const float4*)(W + (size_t)(col0 + r) * K + k0 + lcol);
            uint4 tw;
            tw.x = f2tf32(vw.x); tw.y = f2tf32(vw.y);
            tw.z = f2tf32(vw.z); tw.w = f2tf32(vw.w);
            *(uint4*)&sB[r * 20 + lcol] = tw;
        }
        __syncthreads();

#pragma unroll
        for (int ks = 0; ks < 16; ks += 8) {
            uint32_t a[2][4], b[8][2];
#pragma unroll
            for (int mi = 0; mi < 2; mi++) {
                const int r = wm * 32 + mi * 16 + (lane >> 2);
                const int cc = ks + (lane & 3);
                a[mi][0] = sA[r * 20 + cc];
                a[mi][1] = sA[(r + 8) * 20 + cc];
                a[mi][2] = sA[r * 20 + cc + 4];
                a[mi][3] = sA[(r + 8) * 20 + cc + 4];
            }
#pragma unroll
            for (int ni = 0; ni < 8; ni++) {
                const int n = wn * 64 + ni * 8 + (lane >> 2);
                const int kk = ks + (lane & 3);
                b[ni][0] = sB[n * 20 + kk];
                b[ni][1] = sB[n * 20 + kk + 4];
            }
#pragma unroll
            for (int mi = 0; mi < 2; mi++)
#pragma unroll
                for (int ni = 0; ni < 8; ni++) {
                    asm volatile(
                        "mma.sync.aligned.m16n8k8.row.col.f32.tf32.tf32.f32 "
                        "{%0,%1,%2,%3},{%4,%5,%6,%7},{%8,%9},{%0,%1,%2,%3};\n"
                        : "+f"(c[mi][ni][0]), "+f"(c[mi][ni][1]),
                          "+f"(c[mi][ni][2]), "+f"(c[mi][ni][3])
                        : "r"(a[mi][0]), "r"(a[mi][1]), "r"(a[mi][2]), "r"(a[mi][3]),
                          "r"(b[ni][0]), "r"(b[ni][1]));
                }
        }
    }

    // Epilogue
#pragma unroll
    for (int mi = 0; mi < 2; mi++) {
        const int rbase = row0 + wm * 32 + mi * 16 + (lane >> 2);
#pragma unroll
        for (int ni = 0; ni < 8; ni++) {
            const int col = col0 + wn * 64 + ni * 8 + (lane & 3) * 2;
            const float b0 = bias[col];
            const float b1 = bias[col + 1];
            float v00 = c[mi][ni][0] + b0;
            float v01 = c[mi][ni][1] + b1;
            float v10 = c[mi][ni][2] + b0;
            float v11 = c[mi][ni][3] + b1;
            if (EPI == EPI_RELU) {
                v00 = fmaxf(v00, 0.0f); v01 = fmaxf(v01, 0.0f);
                v10 = fmaxf(v10, 0.0f); v11 = fmaxf(v11, 0.0f);
            }
            const size_t i0 = (size_t)rbase * N + col;
            const size_t i1 = (size_t)(rbase + 8) * N + col;
            C[i0] = v00; C[i0 + 1] = v01;
            C[i1] = v10; C[i1 + 1] = v11;
            if (EPI == EPI_LOGITS) {
                C2[i0] = tanhf(v00); C2[i0 + 1] = tanhf(v01);
                C2[i1] = tanhf(v10); C2[i1 + 1] = tanhf(v11);
            }
        }
    }
}

// ---------------------------------------------------------------------------
// GRU elementwise: state = (1-z)*n + z*state  (PyTorch GRUCell gate order r,z,n)
// ---------------------------------------------------------------------------
__global__ void gru_kernel()
{
    const int idx = blockIdx.x * blockDim.x + threadIdx.x;  // BATCH*LDIM threads
    const int row = idx >> 10;        // LDIM = 1024
    const int j   = idx & 1023;
    const float* xg = g_xg + (size_t)row * (3 * LDIM);
    const float* hg = g_hg + (size_t)row * (3 * LDIM);
    const float xr = xg[j], xz = xg[LDIM + j], xn = xg[2 * LDIM + j];
    const float hr = hg[j], hz = hg[LDIM + j], hn = hg[2 * LDIM + j];
    const float s = g_state[idx];
    const float r = 1.0f / (1.0f + expf(-(xr + hr)));
    const float z = 1.0f / (1.0f + expf(-(xz + hz)));
    const float n = tanhf(xn + r * hn);
    g_state[idx] = (1.0f - z) * n + z * s;
}

// ---------------------------------------------------------------------------
// Halt head: halt[b, 0:2] = h2[b,:] @ hw2[0:2,:]^T + hb2 ; warp per row
// ---------------------------------------------------------------------------
__global__ void halt_kernel(const float* __restrict__ hw2,
                            const float* __restrict__ hb2,
                            float* __restrict__ out)
{
    const int row  = blockIdx.x * (blockDim.x >> 5) + (threadIdx.x >> 5);
    const int lane = threadIdx.x & 31;
    const float* h = g_h2 + (size_t)row * HALTH;
    float s0 = 0.0f, s1 = 0.0f;
    for (int k = lane; k < HALTH; k += 32) {
        const float v = h[k];
        s0 += v * hw2[k];
        s1 += v * hw2[HALTH + k];
    }
#pragma unroll
    for (int o = 16; o > 0; o >>= 1) {
        s0 += __shfl_down_sync(0xFFFFFFFFu, s0, o);
        s1 += __shfl_down_sync(0xFFFFFFFFu, s1, o);
    }
    if (lane == 0) {
        out[(size_t)row * 2]     = s0 + hb2[0];
        out[(size_t)row * 2 + 1] = s1 + hb2[1];
    }
}

// ---------------------------------------------------------------------------
// Host orchestration
// ---------------------------------------------------------------------------
extern "C" void kernel_launch(void* const* d_in, const int* in_sizes, int n_in,
                              void* d_out, int out_size)
{
    const float* inputs = (const float*)d_in[0];
    const float* W_ih   = (const float*)d_in[1];
    const float* W_hh   = (const float*)d_in[2];
    const float* b_ih   = (const float*)d_in[3];
    const float* b_hh   = (const float*)d_in[4];
    const float* aw1    = (const float*)d_in[5];
    const float* ab1    = (const float*)d_in[6];
    const float* aw2    = (const float*)d_in[7];
    const float* ab2    = (const float*)d_in[8];
    const float* hw1    = (const float*)d_in[9];
    const float* hb1    = (const float*)d_in[10];
    const float* hw2    = (const float*)d_in[11];
    const float* hb2    = (const float*)d_in[12];
    // d_in[13]=inner_cycles(4), d_in[14]=outer_steps(8): fixed by setup_inputs.

    float* out = (float*)d_out;
    float* ans_out  = out;                                    // [8, 4096, 512]
    float* halt_out = out + (size_t)OUTER * BATCH * ODIM;     // [8, 4096, 2]

    float *pstate, *pans, *pxg, *phg, *ph1, *ph2;
    cudaGetSymbolAddress((void**)&pstate, g_state);
    cudaGetSymbolAddress((void**)&pans,   g_ans);
    cudaGetSymbolAddress((void**)&pxg,    g_xg);
    cudaGetSymbolAddress((void**)&phg,    g_hg);
    cudaGetSymbolAddress((void**)&ph1,    g_h1);
    cudaGetSymbolAddress((void**)&ph2,    g_h2);

    cudaMemsetAsync(pstate, 0, sizeof(float) * BATCH * LDIM);
    cudaMemsetAsync(pans,   0, sizeof(float) * BATCH * ODIM);

    const dim3 blk(256);
    const int MR = BATCH / 128;  // 32 row blocks

    for (int s = 0; s < OUTER; s++) {
        // x_gates = concat(inputs, ans) @ W_ih^T + b_ih     [B, 3L]
        gemm_tf32<EPI_NONE><<<dim3((3 * LDIM) / 128, MR), blk>>>(
            inputs, IDIM, IDIM, pans, ODIM, W_ih, b_ih,
            pxg, nullptr, 3 * LDIM, IDIM + ODIM);

        for (int i = 0; i < INNER; i++) {
            // h_gates = state @ W_hh^T + b_hh               [B, 3L]
            gemm_tf32<EPI_NONE><<<dim3((3 * LDIM) / 128, MR), blk>>>(
                pstate, LDIM, LDIM, pstate, LDIM, W_hh, b_hh,
                phg, nullptr, 3 * LDIM, LDIM);
            gru_kernel<<<(BATCH * LDIM) / 256, 256>>>();
        }

        // h1 = relu(concat(state, ans) @ aw1^T + ab1)       [B, H]
        gemm_tf32<EPI_RELU><<<dim3(HDIM / 128, MR), blk>>>(
            pstate, LDIM, LDIM, pans, ODIM, aw1, ab1,
            ph1, nullptr, HDIM, LDIM + ODIM);

        // h2 = relu(concat(state, ans) @ hw1^T + hb1)       [B, HALT_H]
        gemm_tf32<EPI_RELU><<<dim3(HALTH / 128, MR), blk>>>(
            pstate, LDIM, LDIM, pans, ODIM, hw1, hb1,
            ph2, nullptr, HALTH, LDIM + ODIM);

        // halt = h2 @ hw2^T + hb2                           [B, 2]
        halt_kernel<<<BATCH / 8, 256>>>(hw2, hb2, halt_out + (size_t)s * BATCH * 2);

        // logits = h1 @ aw2^T + ab2 -> out; ans = tanh(logits)   (LAST: overwrites ans)
        gemm_tf32<EPI_LOGITS><<<dim3(ODIM / 128, MR), blk>>>(
            ph1, HDIM, HDIM, ph1, HDIM, aw2, ab2,
            ans_out + (size_t)s * BATCH * ODIM, pans, ODIM, HDIM);
    }
}